// round 7
// baseline (speedup 1.0000x reference)
#include <cuda_runtime.h>
#include <cuda_bf16.h>
#include <math.h>

#define NMAX 50000
#define EMAX 800000
#define HID  128
#define CO   40

// ---------------- scratch (device globals) ----------------
__device__ __align__(16) float g_bufA[NMAX * HID];
__device__ __align__(16) float g_bufB[NMAX * HID];
__device__ __align__(16) float g_h3[NMAX * CO];
__device__ __align__(16) float g_agg3[NMAX * CO];
__device__ __align__(16) float g_dinv[NMAX];
__device__ int   g_cnt[NMAX];
__device__ int   g_off[NMAX + 1];
__device__ int   g_cur[NMAX];
__device__ int   g_bsum[128];
__device__ int   g_csr_src[EMAX + NMAX];
__device__ float g_csr_coef[EMAX + NMAX];
__device__ __align__(16) float g_stats[2 * HID];
__device__ __align__(16) float g_coef[2 * HID];

// ---------------- degree ----------------
__global__ void deg_init(int n) {
    int i = blockIdx.x * blockDim.x + threadIdx.x;
    if (i < n) g_cnt[i] = 1;
}
__global__ void deg_count(const int* __restrict__ ei, int e) {
    int i = blockIdx.x * blockDim.x + threadIdx.x;
    if (i < e) atomicAdd(&g_cnt[ei[e + i]], 1);
}
__global__ void deg_finish(int n) {
    int i = blockIdx.x * blockDim.x + threadIdx.x;
    if (i < n) g_dinv[i] = rsqrtf((float)g_cnt[i]);
}

// ---------------- exclusive scan of g_cnt -> g_off (warp-shuffle) ----------
__global__ void scanA(int n) {
    __shared__ int wsum[32];
    const unsigned FULL = 0xffffffffu;
    int i = blockIdx.x * 1024 + threadIdx.x;
    int lane = threadIdx.x & 31, wid = threadIdx.x >> 5;
    int x = (i < n) ? g_cnt[i] : 0;
#pragma unroll
    for (int o = 1; o < 32; o <<= 1) {
        int t = __shfl_up_sync(FULL, x, o);
        if (lane >= o) x += t;
    }
    if (lane == 31) wsum[wid] = x;
    __syncthreads();
    if (wid == 0) {
        int y = wsum[lane];
#pragma unroll
        for (int o = 1; o < 32; o <<= 1) {
            int t = __shfl_up_sync(FULL, y, o);
            if (lane >= o) y += t;
        }
        wsum[lane] = y;
    }
    __syncthreads();
    int inc = x + (wid ? wsum[wid - 1] : 0);
    if (i < n) g_off[i + 1] = inc;
    if (threadIdx.x == 1023) g_bsum[blockIdx.x] = inc;
}
// single-warp exclusive scan of up to 64 block sums (pairs per lane)
__global__ void scanB(int nb) {
    const unsigned FULL = 0xffffffffu;
    int lane = threadIdx.x;
    int i0 = 2 * lane, i1 = 2 * lane + 1;
    int v0 = (i0 < nb) ? g_bsum[i0] : 0;
    int v1 = (i1 < nb) ? g_bsum[i1] : 0;
    int s = v0 + v1;
    int x = s;
#pragma unroll
    for (int o = 1; o < 32; o <<= 1) {
        int t = __shfl_up_sync(FULL, x, o);
        if (lane >= o) x += t;
    }
    int base = x - s;  // exclusive
    if (i0 < nb) g_bsum[i0] = base;
    if (i1 < nb) g_bsum[i1] = base + v0;
}
__global__ void scanC(int n) {
    int i = blockIdx.x * 1024 + threadIdx.x;
    if (i < n) g_off[i + 1] += g_bsum[blockIdx.x];
    if (i == 0) g_off[0] = 0;
}
// merged cursor-init + self-loop scatter (self entry is first, deterministic)
__global__ void self_scatter(int n) {
    int i = blockIdx.x * blockDim.x + threadIdx.x;
    if (i < n) {
        int o = g_off[i];
        g_cur[i] = o + 1;
        g_csr_src[o] = i;
        float di = g_dinv[i];
        g_csr_coef[o] = di * di;
    }
}
__global__ void scatter_edges(const int* __restrict__ ei, int e) {
    int i = blockIdx.x * blockDim.x + threadIdx.x;
    if (i < e) {
        int s = ei[i];
        int d = ei[e + i];
        int p = atomicAdd(&g_cur[d], 1);
        g_csr_src[p] = s;
        g_csr_coef[p] = g_dinv[s] * g_dinv[d];
    }
}

// ---------------- SGEMM 128x128: BM=128 BN=128 BK=16, 256 thr, 8x8/thread --
template <int BN>
__global__ __launch_bounds__(256) void gemm128_kernel(
    const float* __restrict__ A, const float* __restrict__ W,
    float* __restrict__ C, int M) {
    __shared__ float As[16][132];   // k-major, padded
    __shared__ float Bs[16][128];
    const int tid = threadIdx.x;
    const int tx = tid & 15;        // 16 col groups of 8
    const int ty = tid >> 4;        // 16 row groups of 8
    const int row0 = blockIdx.x * 128;

    float acc[8][8];
#pragma unroll
    for (int i = 0; i < 8; i++)
#pragma unroll
        for (int j = 0; j < 8; j++) acc[i][j] = 0.0f;

    const int am = tid >> 1;              // 0..127
    const int ak = (tid & 1) << 3;        // 0 or 8

    for (int kk = 0; kk < 128; kk += 16) {
        // A tile: 128 x 16, two float4 per thread, store transposed + BN fuse
        int gr = row0 + am;
#pragma unroll
        for (int h = 0; h < 2; h++) {
            float4 av = make_float4(0.f, 0.f, 0.f, 0.f);
            int col = kk + ak + h * 4;
            if (gr < M) av = *(const float4*)(A + (size_t)gr * 128 + col);
            if (BN) {
                float4 s = ((const float4*)g_coef)[col >> 2];
                float4 t = ((const float4*)g_coef)[32 + (col >> 2)];
                av.x = fmaxf(fmaf(av.x, s.x, t.x), 0.f);
                av.y = fmaxf(fmaf(av.y, s.y, t.y), 0.f);
                av.z = fmaxf(fmaf(av.z, s.z, t.z), 0.f);
                av.w = fmaxf(fmaf(av.w, s.w, t.w), 0.f);
            }
            As[ak + h * 4 + 0][am] = av.x;
            As[ak + h * 4 + 1][am] = av.y;
            As[ak + h * 4 + 2][am] = av.z;
            As[ak + h * 4 + 3][am] = av.w;
        }
        // B tile: 16 x 128, two float4 per thread
#pragma unroll
        for (int i = 0; i < 2; i++) {
            int v = tid + i * 256;
            int br = v >> 5, bc = (v & 31) << 2;
            *(float4*)&Bs[br][bc] = *(const float4*)(W + (size_t)(kk + br) * 128 + bc);
        }
        __syncthreads();
#pragma unroll
        for (int k = 0; k < 16; k++) {
            float4 a0 = *(float4*)&As[k][ty << 3];
            float4 a1 = *(float4*)&As[k][(ty << 3) + 4];
            float4 b0 = *(float4*)&Bs[k][tx << 3];
            float4 b1 = *(float4*)&Bs[k][(tx << 3) + 4];
            float ar[8] = {a0.x, a0.y, a0.z, a0.w, a1.x, a1.y, a1.z, a1.w};
            float br[8] = {b0.x, b0.y, b0.z, b0.w, b1.x, b1.y, b1.z, b1.w};
#pragma unroll
            for (int i = 0; i < 8; i++)
#pragma unroll
                for (int j = 0; j < 8; j++)
                    acc[i][j] = fmaf(ar[i], br[j], acc[i][j]);
        }
        __syncthreads();
    }
#pragma unroll
    for (int i = 0; i < 8; i++) {
        int gr = row0 + (ty << 3) + i;
        if (gr < M) {
            float4* cp = (float4*)(C + (size_t)gr * 128 + (tx << 3));
            cp[0] = make_float4(acc[i][0], acc[i][1], acc[i][2], acc[i][3]);
            cp[1] = make_float4(acc[i][4], acc[i][5], acc[i][6], acc[i][7]);
        }
    }
}

// ---------------- SGEMM 128x40 with fused BN+ReLU on A ---------------------
__global__ void gemm40_kernel(const float* __restrict__ A,
                              const float* __restrict__ W,
                              float* __restrict__ C, int M) {
    __shared__ float Xs[32][133];
    __shared__ float Ws[128 * 40];
    const int tid = threadIdx.x;
    const int row0 = blockIdx.x * 32;

    for (int i = tid; i < 128 * 40; i += 256) Ws[i] = W[i];
#pragma unroll
    for (int i = 0; i < 4; i++) {
        int v = tid + i * 256;
        int r = v >> 5, c = (v & 31) << 2;
        float4 xv = make_float4(0.f, 0.f, 0.f, 0.f);
        int gr = row0 + r;
        if (gr < M) xv = *(const float4*)(A + (size_t)gr * 128 + c);
        float4 s = ((const float4*)g_coef)[c >> 2];
        float4 t = ((const float4*)g_coef)[32 + (c >> 2)];
        Xs[r][c + 0] = fmaxf(fmaf(xv.x, s.x, t.x), 0.f);
        Xs[r][c + 1] = fmaxf(fmaf(xv.y, s.y, t.y), 0.f);
        Xs[r][c + 2] = fmaxf(fmaf(xv.z, s.z, t.z), 0.f);
        Xs[r][c + 3] = fmaxf(fmaf(xv.w, s.w, t.w), 0.f);
    }
    __syncthreads();

    const int r = tid >> 3;
    const int cg = tid & 7;
    float acc[5] = {0.f, 0.f, 0.f, 0.f, 0.f};
#pragma unroll 8
    for (int k = 0; k < 128; k++) {
        float xv = Xs[r][k];
        const float* wr = &Ws[k * 40 + cg * 5];
#pragma unroll
        for (int c = 0; c < 5; c++) acc[c] = fmaf(xv, wr[c], acc[c]);
    }
    int gr = row0 + r;
    if (gr < M) {
        float* out = C + (size_t)gr * 40 + cg * 5;
#pragma unroll
        for (int c = 0; c < 5; c++) out[c] = acc[c];
    }
}

// -------- CSR gather aggregation, optional fused BN-stats reduction --------
template <int STATS>
__global__ __launch_bounds__(256) void agg_csr128(
    const float* __restrict__ H, float* __restrict__ Agg, int n) {
    __shared__ float sh_s[128], sh_s2[128];
    if (STATS) {
        if (threadIdx.x < 128) { sh_s[threadIdx.x] = 0.f; sh_s2[threadIdx.x] = 0.f; }
        __syncthreads();
    }
    int warp = (blockIdx.x * blockDim.x + threadIdx.x) >> 5;
    int lane = threadIdx.x & 31;
    float4 acc = make_float4(0.f, 0.f, 0.f, 0.f);
    bool active = (warp < n);
    if (active) {
        int beg = g_off[warp], end = g_off[warp + 1];
        int e = beg;
        for (; e + 3 < end; e += 4) {
            int   s0 = g_csr_src[e],     s1 = g_csr_src[e + 1];
            int   s2 = g_csr_src[e + 2], s3 = g_csr_src[e + 3];
            float c0 = g_csr_coef[e],    c1 = g_csr_coef[e + 1];
            float c2 = g_csr_coef[e + 2], c3 = g_csr_coef[e + 3];
            float4 v0 = ((const float4*)(H + (size_t)s0 * 128))[lane];
            float4 v1 = ((const float4*)(H + (size_t)s1 * 128))[lane];
            float4 v2 = ((const float4*)(H + (size_t)s2 * 128))[lane];
            float4 v3 = ((const float4*)(H + (size_t)s3 * 128))[lane];
            acc.x = fmaf(v0.x, c0, fmaf(v1.x, c1, fmaf(v2.x, c2, fmaf(v3.x, c3, acc.x))));
            acc.y = fmaf(v0.y, c0, fmaf(v1.y, c1, fmaf(v2.y, c2, fmaf(v3.y, c3, acc.y))));
            acc.z = fmaf(v0.z, c0, fmaf(v1.z, c1, fmaf(v2.z, c2, fmaf(v3.z, c3, acc.z))));
            acc.w = fmaf(v0.w, c0, fmaf(v1.w, c1, fmaf(v2.w, c2, fmaf(v3.w, c3, acc.w))));
        }
        for (; e < end; e++) {
            int s0 = g_csr_src[e];
            float c0 = g_csr_coef[e];
            float4 v0 = ((const float4*)(H + (size_t)s0 * 128))[lane];
            acc.x = fmaf(v0.x, c0, acc.x);
            acc.y = fmaf(v0.y, c0, acc.y);
            acc.z = fmaf(v0.z, c0, acc.z);
            acc.w = fmaf(v0.w, c0, acc.w);
        }
        ((float4*)(Agg + (size_t)warp * 128))[lane] = acc;
    }
    if (STATS) {
        if (active) {
            int col = lane << 2;
            atomicAdd(&sh_s[col + 0], acc.x);  atomicAdd(&sh_s2[col + 0], acc.x * acc.x);
            atomicAdd(&sh_s[col + 1], acc.y);  atomicAdd(&sh_s2[col + 1], acc.y * acc.y);
            atomicAdd(&sh_s[col + 2], acc.z);  atomicAdd(&sh_s2[col + 2], acc.z * acc.z);
            atomicAdd(&sh_s[col + 3], acc.w);  atomicAdd(&sh_s2[col + 3], acc.w * acc.w);
        }
        __syncthreads();
        if (threadIdx.x < 128) {
            atomicAdd(&g_stats[threadIdx.x], sh_s[threadIdx.x]);
            atomicAdd(&g_stats[128 + threadIdx.x], sh_s2[threadIdx.x]);
        }
    }
}

__global__ void agg_csr40(const float* __restrict__ H,
                          float* __restrict__ Agg, int n) {
    int warp = (blockIdx.x * blockDim.x + threadIdx.x) >> 5;
    int lane = threadIdx.x & 31;
    if (warp >= n) return;
    int beg = g_off[warp], end = g_off[warp + 1];
    float4 acc = make_float4(0.f, 0.f, 0.f, 0.f);
    for (int e = beg; e < end; e++) {
        int s0 = g_csr_src[e];
        float c0 = g_csr_coef[e];
        if (lane < 10) {
            float4 v0 = ((const float4*)(H + (size_t)s0 * 40))[lane];
            acc.x = fmaf(v0.x, c0, acc.x);
            acc.y = fmaf(v0.y, c0, acc.y);
            acc.z = fmaf(v0.z, c0, acc.z);
            acc.w = fmaf(v0.w, c0, acc.w);
        }
    }
    if (lane < 10) ((float4*)(Agg + (size_t)warp * 40))[lane] = acc;
}

// ---------------- BN coefficients ----------------
__global__ void zero_stats() {
    if (threadIdx.x < 256) g_stats[threadIdx.x] = 0.0f;
}
__global__ void bn_coef(const float* __restrict__ gamma,
                        const float* __restrict__ beta, float invM) {
    int f = threadIdx.x;
    float mu = g_stats[f] * invM;
    float var = g_stats[128 + f] * invM - mu * mu;
    float scl = gamma[f] * rsqrtf(var + 1e-5f);
    g_coef[f] = scl;
    g_coef[128 + f] = beta[f] - mu * scl;
}

// ---------------- log-softmax ----------------
__global__ void logsm_kernel(const float* __restrict__ A,
                             const float* __restrict__ b3,
                             float* __restrict__ out, int M) {
    int lane = threadIdx.x & 31;
    int row = (blockIdx.x * blockDim.x + threadIdx.x) >> 5;
    if (row >= M) return;
    const float* x = A + (size_t)row * 40;
    float v0 = x[lane] + b3[lane];
    float v1 = (lane < 8) ? x[32 + lane] + b3[32 + lane] : -3.0e38f;
    float mx = fmaxf(v0, v1);
#pragma unroll
    for (int o = 16; o; o >>= 1) mx = fmaxf(mx, __shfl_xor_sync(0xffffffffu, mx, o));
    float se = expf(v0 - mx) + ((lane < 8) ? expf(v1 - mx) : 0.f);
#pragma unroll
    for (int o = 16; o; o >>= 1) se += __shfl_xor_sync(0xffffffffu, se, o);
    float lse = logf(se);
    out[(size_t)row * 40 + lane] = v0 - mx - lse;
    if (lane < 8) out[(size_t)row * 40 + 32 + lane] = v1 - mx - lse;
}

// ---------------- launch ----------------
extern "C" void kernel_launch(void* const* d_in, const int* in_sizes, int n_in,
                              void* d_out, int out_size) {
    const float* feats = (const float*)d_in[0];
    const int*   ei    = (const int*)d_in[1];
    const float* W1 = (const float*)d_in[2];
    const float* g1 = (const float*)d_in[4];
    const float* be1 = (const float*)d_in[5];
    const float* W2 = (const float*)d_in[6];
    const float* g2 = (const float*)d_in[8];
    const float* be2 = (const float*)d_in[9];
    const float* W3 = (const float*)d_in[10];
    const float* b3 = (const float*)d_in[11];
    float* out = (float*)d_out;

    const int Nn = in_sizes[0] / HID;
    const int Ee = in_sizes[1] / 2;

    float *bufA, *bufB, *h3, *agg3;
    cudaGetSymbolAddress((void**)&bufA, g_bufA);
    cudaGetSymbolAddress((void**)&bufB, g_bufB);
    cudaGetSymbolAddress((void**)&h3, g_h3);
    cudaGetSymbolAddress((void**)&agg3, g_agg3);

    const float invM = 1.0f / (float)Nn;
    const int nb = (Nn + 1023) / 1024;
    const int AGG_BLOCKS = (Nn + 7) / 8;

    // ---- degree + CSR build ----
    deg_init<<<(Nn + 255) / 256, 256>>>(Nn);
    deg_count<<<(Ee + 255) / 256, 256>>>(ei, Ee);
    deg_finish<<<(Nn + 255) / 256, 256>>>(Nn);
    scanA<<<nb, 1024>>>(Nn);
    scanB<<<1, 32>>>(nb);
    scanC<<<nb, 1024>>>(Nn);
    self_scatter<<<(Nn + 255) / 256, 256>>>(Nn);
    scatter_edges<<<(Ee + 255) / 256, 256>>>(ei, Ee);

    // ---- layer 1 ----
    gemm128_kernel<0><<<(Nn + 127) / 128, 256>>>(feats, W1, bufA, Nn);
    zero_stats<<<1, 256>>>();
    agg_csr128<1><<<AGG_BLOCKS, 256>>>(bufA, bufB, Nn);
    bn_coef<<<1, 128>>>(g1, be1, invM);

    // ---- layer 2 (BN1+ReLU fused into A-load) ----
    gemm128_kernel<1><<<(Nn + 127) / 128, 256>>>(bufB, W2, bufA, Nn);
    zero_stats<<<1, 256>>>();
    agg_csr128<1><<<AGG_BLOCKS, 256>>>(bufA, bufB, Nn);
    bn_coef<<<1, 128>>>(g2, be2, invM);

    // ---- layer 3 (BN2+ReLU fused into A-load) ----
    gemm40_kernel<<<(Nn + 31) / 32, 256>>>(bufB, W3, h3, Nn);
    agg_csr40<<<AGG_BLOCKS, 256>>>(h3, agg3, Nn);
    logsm_kernel<<<(Nn * 32 + 255) / 256, 256>>>(agg3, b3, out, Nn);
}

// round 9
// speedup vs baseline: 1.1343x; 1.1343x over previous
#include <cuda_runtime.h>
#include <cuda_fp16.h>
#include <math.h>

#define NMAX 50000
#define EMAX 800000
#define HID  128
#define CO   40

// ---------------- scratch (device globals) ----------------
__device__ __align__(16) float  g_bufB[NMAX * HID];     // fp32 agg output
__device__ __align__(16) __half g_hA[NMAX * HID];       // fp16 gemm output (gather src)
__device__ __align__(16) __half g_h3[NMAX * CO];        // fp16 layer-3 gemm output
__device__ __align__(16) float  g_dinv[NMAX];
__device__ int   g_cnt[NMAX];
__device__ int   g_off[NMAX + 1];
__device__ int   g_cur[NMAX];
__device__ int   g_bsum[128];
__device__ int   g_csr_src[EMAX + NMAX];
__device__ float g_csr_coef[EMAX + NMAX];
__device__ __align__(16) float g_stats[2 * HID];
__device__ __align__(16) float g_coef[2 * HID];

// ---------------- degree (also zeroes BN stats) ----------------
__global__ void deg_init(int n) {
    int i = blockIdx.x * blockDim.x + threadIdx.x;
    if (i < n) g_cnt[i] = 1;               // self loop
    if (i < 256) g_stats[i] = 0.0f;
}
__global__ void deg_count(const int* __restrict__ ei, int e) {
    int i = blockIdx.x * blockDim.x + threadIdx.x;
    if (i < e) atomicAdd(&g_cnt[ei[e + i]], 1);
}

// -------- scanA: block-level inclusive scan of cnt; also writes dinv -------
__global__ void scanA(int n) {
    __shared__ int wsum[32];
    const unsigned FULL = 0xffffffffu;
    int i = blockIdx.x * 1024 + threadIdx.x;
    int lane = threadIdx.x & 31, wid = threadIdx.x >> 5;
    int c = (i < n) ? g_cnt[i] : 0;
    if (i < n) g_dinv[i] = rsqrtf((float)c);
    int x = c;
#pragma unroll
    for (int o = 1; o < 32; o <<= 1) {
        int t = __shfl_up_sync(FULL, x, o);
        if (lane >= o) x += t;
    }
    if (lane == 31) wsum[wid] = x;
    __syncthreads();
    if (wid == 0) {
        int y = wsum[lane];
#pragma unroll
        for (int o = 1; o < 32; o <<= 1) {
            int t = __shfl_up_sync(FULL, y, o);
            if (lane >= o) y += t;
        }
        wsum[lane] = y;
    }
    __syncthreads();
    int inc = x + (wid ? wsum[wid - 1] : 0);
    if (i < n) g_off[i + 1] = inc;
    if (threadIdx.x == 1023) g_bsum[blockIdx.x] = inc;
}
// single-warp exclusive scan of up to 64 block sums
__global__ void scanB(int nb) {
    const unsigned FULL = 0xffffffffu;
    int lane = threadIdx.x;
    int i0 = 2 * lane, i1 = 2 * lane + 1;
    int v0 = (i0 < nb) ? g_bsum[i0] : 0;
    int v1 = (i1 < nb) ? g_bsum[i1] : 0;
    int s = v0 + v1;
    int x = s;
#pragma unroll
    for (int o = 1; o < 32; o <<= 1) {
        int t = __shfl_up_sync(FULL, x, o);
        if (lane >= o) x += t;
    }
    int base = x - s;
    if (i0 < nb) g_bsum[i0] = base;
    if (i1 < nb) g_bsum[i1] = base + v0;
}
// scanC: finalize offsets + cursor init + self-loop scatter in one pass
__global__ void scanC(int n) {
    int i = blockIdx.x * 1024 + threadIdx.x;
    if (i < n) {
        int o = g_off[i + 1] + g_bsum[blockIdx.x];
        g_off[i + 1] = o;
        int p = o - g_cnt[i];        // exclusive offset of node i
        g_cur[i] = p + 1;
        g_csr_src[p] = i;
        float di = g_dinv[i];
        g_csr_coef[p] = di * di;
    }
    if (i == 0) g_off[0] = 0;
}
__global__ void scatter_edges(const int* __restrict__ ei, int e) {
    int i = blockIdx.x * blockDim.x + threadIdx.x;
    if (i < e) {
        int s = ei[i];
        int d = ei[e + i];
        int p = atomicAdd(&g_cur[d], 1);
        g_csr_src[p] = s;
        g_csr_coef[p] = g_dinv[s] * g_dinv[d];
    }
}

// ---- SGEMM 128x128 -> fp16 out: BM=128 BN=128 BK=16, 256 thr, 8x8/thread --
template <int BN>
__global__ __launch_bounds__(256) void gemm128_kernel(
    const float* __restrict__ A, const float* __restrict__ W,
    __half* __restrict__ C, int M) {
    __shared__ float As[16][132];
    __shared__ float Bs[16][128];
    const int tid = threadIdx.x;
    const int tx = tid & 15;
    const int ty = tid >> 4;
    const int row0 = blockIdx.x * 128;

    float acc[8][8];
#pragma unroll
    for (int i = 0; i < 8; i++)
#pragma unroll
        for (int j = 0; j < 8; j++) acc[i][j] = 0.0f;

    const int am = tid >> 1;
    const int ak = (tid & 1) << 3;

    for (int kk = 0; kk < 128; kk += 16) {
        int gr = row0 + am;
#pragma unroll
        for (int h = 0; h < 2; h++) {
            float4 av = make_float4(0.f, 0.f, 0.f, 0.f);
            int col = kk + ak + h * 4;
            if (gr < M) av = *(const float4*)(A + (size_t)gr * 128 + col);
            if (BN) {
                float4 s = ((const float4*)g_coef)[col >> 2];
                float4 t = ((const float4*)g_coef)[32 + (col >> 2)];
                av.x = fmaxf(fmaf(av.x, s.x, t.x), 0.f);
                av.y = fmaxf(fmaf(av.y, s.y, t.y), 0.f);
                av.z = fmaxf(fmaf(av.z, s.z, t.z), 0.f);
                av.w = fmaxf(fmaf(av.w, s.w, t.w), 0.f);
            }
            As[ak + h * 4 + 0][am] = av.x;
            As[ak + h * 4 + 1][am] = av.y;
            As[ak + h * 4 + 2][am] = av.z;
            As[ak + h * 4 + 3][am] = av.w;
        }
#pragma unroll
        for (int i = 0; i < 2; i++) {
            int v = tid + i * 256;
            int br = v >> 5, bc = (v & 31) << 2;
            *(float4*)&Bs[br][bc] = *(const float4*)(W + (size_t)(kk + br) * 128 + bc);
        }
        __syncthreads();
#pragma unroll
        for (int k = 0; k < 16; k++) {
            float4 a0 = *(float4*)&As[k][ty << 3];
            float4 a1 = *(float4*)&As[k][(ty << 3) + 4];
            float4 b0 = *(float4*)&Bs[k][tx << 3];
            float4 b1 = *(float4*)&Bs[k][(tx << 3) + 4];
            float ar[8] = {a0.x, a0.y, a0.z, a0.w, a1.x, a1.y, a1.z, a1.w};
            float br[8] = {b0.x, b0.y, b0.z, b0.w, b1.x, b1.y, b1.z, b1.w};
#pragma unroll
            for (int i = 0; i < 8; i++)
#pragma unroll
                for (int j = 0; j < 8; j++)
                    acc[i][j] = fmaf(ar[i], br[j], acc[i][j]);
        }
        __syncthreads();
    }
    // store 8 cols per row as half8 (uint4)
#pragma unroll
    for (int i = 0; i < 8; i++) {
        int gr = row0 + (ty << 3) + i;
        if (gr < M) {
            __half2 h01 = __floats2half2_rn(acc[i][0], acc[i][1]);
            __half2 h23 = __floats2half2_rn(acc[i][2], acc[i][3]);
            __half2 h45 = __floats2half2_rn(acc[i][4], acc[i][5]);
            __half2 h67 = __floats2half2_rn(acc[i][6], acc[i][7]);
            uint4 pk;
            pk.x = *(unsigned*)&h01; pk.y = *(unsigned*)&h23;
            pk.z = *(unsigned*)&h45; pk.w = *(unsigned*)&h67;
            *(uint4*)(C + (size_t)gr * 128 + (tx << 3)) = pk;
        }
    }
}

// ---------------- SGEMM 128x40 (BN+ReLU fused on A) -> fp16 out ------------
__global__ void gemm40_kernel(const float* __restrict__ A,
                              const float* __restrict__ W,
                              __half* __restrict__ C, int M) {
    __shared__ float Xs[32][133];
    __shared__ float Ws[128 * 40];
    const int tid = threadIdx.x;
    const int row0 = blockIdx.x * 32;

    for (int i = tid; i < 128 * 40; i += 256) Ws[i] = W[i];
#pragma unroll
    for (int i = 0; i < 4; i++) {
        int v = tid + i * 256;
        int r = v >> 5, c = (v & 31) << 2;
        float4 xv = make_float4(0.f, 0.f, 0.f, 0.f);
        int gr = row0 + r;
        if (gr < M) xv = *(const float4*)(A + (size_t)gr * 128 + c);
        float4 s = ((const float4*)g_coef)[c >> 2];
        float4 t = ((const float4*)g_coef)[32 + (c >> 2)];
        Xs[r][c + 0] = fmaxf(fmaf(xv.x, s.x, t.x), 0.f);
        Xs[r][c + 1] = fmaxf(fmaf(xv.y, s.y, t.y), 0.f);
        Xs[r][c + 2] = fmaxf(fmaf(xv.z, s.z, t.z), 0.f);
        Xs[r][c + 3] = fmaxf(fmaf(xv.w, s.w, t.w), 0.f);
    }
    __syncthreads();

    const int r = tid >> 3;
    const int cg = tid & 7;
    float acc[5] = {0.f, 0.f, 0.f, 0.f, 0.f};
#pragma unroll 8
    for (int k = 0; k < 128; k++) {
        float xv = Xs[r][k];
        const float* wr = &Ws[k * 40 + cg * 5];
#pragma unroll
        for (int c = 0; c < 5; c++) acc[c] = fmaf(xv, wr[c], acc[c]);
    }
    int gr = row0 + r;
    if (gr < M) {
        __half* outp = C + (size_t)gr * 40 + cg * 5;
#pragma unroll
        for (int c = 0; c < 5; c++) outp[c] = __float2half_rn(acc[c]);
    }
}

// ---- CSR gather aggregation from fp16 H, fused BN-stats, fp32 out ---------
__global__ __launch_bounds__(256) void agg_csr128(
    const __half* __restrict__ H, float* __restrict__ Agg, int n) {
    __shared__ float sh_s[128], sh_s2[128];
    if (threadIdx.x < 128) { sh_s[threadIdx.x] = 0.f; sh_s2[threadIdx.x] = 0.f; }
    __syncthreads();
    int warp = (blockIdx.x * blockDim.x + threadIdx.x) >> 5;
    int lane = threadIdx.x & 31;
    float4 acc = make_float4(0.f, 0.f, 0.f, 0.f);
    bool active = (warp < n);
    if (active) {
        int beg = g_off[warp], end = g_off[warp + 1];
        int e = beg;
        for (; e + 3 < end; e += 4) {
            int   s0 = g_csr_src[e],      s1 = g_csr_src[e + 1];
            int   s2 = g_csr_src[e + 2],  s3 = g_csr_src[e + 3];
            float c0 = g_csr_coef[e],     c1 = g_csr_coef[e + 1];
            float c2 = g_csr_coef[e + 2], c3 = g_csr_coef[e + 3];
            uint2 r0 = ((const uint2*)(H + (size_t)s0 * 128))[lane];
            uint2 r1 = ((const uint2*)(H + (size_t)s1 * 128))[lane];
            uint2 r2 = ((const uint2*)(H + (size_t)s2 * 128))[lane];
            uint2 r3 = ((const uint2*)(H + (size_t)s3 * 128))[lane];
            float2 a0 = __half22float2(*(__half2*)&r0.x), b0 = __half22float2(*(__half2*)&r0.y);
            float2 a1 = __half22float2(*(__half2*)&r1.x), b1 = __half22float2(*(__half2*)&r1.y);
            float2 a2 = __half22float2(*(__half2*)&r2.x), b2 = __half22float2(*(__half2*)&r2.y);
            float2 a3 = __half22float2(*(__half2*)&r3.x), b3v = __half22float2(*(__half2*)&r3.y);
            acc.x = fmaf(a0.x, c0, fmaf(a1.x, c1, fmaf(a2.x, c2, fmaf(a3.x, c3, acc.x))));
            acc.y = fmaf(a0.y, c0, fmaf(a1.y, c1, fmaf(a2.y, c2, fmaf(a3.y, c3, acc.y))));
            acc.z = fmaf(b0.x, c0, fmaf(b1.x, c1, fmaf(b2.x, c2, fmaf(b3v.x, c3, acc.z))));
            acc.w = fmaf(b0.y, c0, fmaf(b1.y, c1, fmaf(b2.y, c2, fmaf(b3v.y, c3, acc.w))));
        }
        for (; e < end; e++) {
            int s0 = g_csr_src[e];
            float c0 = g_csr_coef[e];
            uint2 r0 = ((const uint2*)(H + (size_t)s0 * 128))[lane];
            float2 a0 = __half22float2(*(__half2*)&r0.x), b0 = __half22float2(*(__half2*)&r0.y);
            acc.x = fmaf(a0.x, c0, acc.x);
            acc.y = fmaf(a0.y, c0, acc.y);
            acc.z = fmaf(b0.x, c0, acc.z);
            acc.w = fmaf(b0.y, c0, acc.w);
        }
        ((float4*)(Agg + (size_t)warp * 128))[lane] = acc;
    }
    // BN stats: columns for this lane are 4*lane .. 4*lane+3
    if (active) {
        int col = lane << 2;
        atomicAdd(&sh_s[col + 0], acc.x);  atomicAdd(&sh_s2[col + 0], acc.x * acc.x);
        atomicAdd(&sh_s[col + 1], acc.y);  atomicAdd(&sh_s2[col + 1], acc.y * acc.y);
        atomicAdd(&sh_s[col + 2], acc.z);  atomicAdd(&sh_s2[col + 2], acc.z * acc.z);
        atomicAdd(&sh_s[col + 3], acc.w);  atomicAdd(&sh_s2[col + 3], acc.w * acc.w);
    }
    __syncthreads();
    if (threadIdx.x < 128) {
        atomicAdd(&g_stats[threadIdx.x], sh_s[threadIdx.x]);
        atomicAdd(&g_stats[128 + threadIdx.x], sh_s2[threadIdx.x]);
    }
}

// ---- fused agg40 + bias + log-softmax: warp per node ----------------------
__global__ void agg40_logsm(const __half* __restrict__ H,
                            const float* __restrict__ b3,
                            float* __restrict__ out, int n) {
    const unsigned FULL = 0xffffffffu;
    int warp = (blockIdx.x * blockDim.x + threadIdx.x) >> 5;
    int lane = threadIdx.x & 31;
    if (warp >= n) return;
    int beg = g_off[warp], end = g_off[warp + 1];
    float4 acc = make_float4(0.f, 0.f, 0.f, 0.f);
    for (int e = beg; e < end; e++) {
        int s0 = g_csr_src[e];
        float c0 = g_csr_coef[e];
        if (lane < 10) {
            uint2 r0 = ((const uint2*)(H + (size_t)s0 * 40))[lane];
            float2 a0 = __half22float2(*(__half2*)&r0.x);
            float2 b0 = __half22float2(*(__half2*)&r0.y);
            acc.x = fmaf(a0.x, c0, acc.x);
            acc.y = fmaf(a0.y, c0, acc.y);
            acc.z = fmaf(b0.x, c0, acc.z);
            acc.w = fmaf(b0.y, c0, acc.w);
        }
    }
    float4 v = make_float4(-3.0e38f, -3.0e38f, -3.0e38f, -3.0e38f);
    if (lane < 10) {
        float4 bb = ((const float4*)b3)[lane];
        v = make_float4(acc.x + bb.x, acc.y + bb.y, acc.z + bb.z, acc.w + bb.w);
    }
    float mx = fmaxf(fmaxf(v.x, v.y), fmaxf(v.z, v.w));
#pragma unroll
    for (int o = 16; o; o >>= 1) mx = fmaxf(mx, __shfl_xor_sync(FULL, mx, o));
    float se = 0.f;
    if (lane < 10)
        se = expf(v.x - mx) + expf(v.y - mx) + expf(v.z - mx) + expf(v.w - mx);
#pragma unroll
    for (int o = 16; o; o >>= 1) se += __shfl_xor_sync(FULL, se, o);
    float sh = mx + logf(se);
    if (lane < 10)
        ((float4*)(out + (size_t)warp * 40))[lane] =
            make_float4(v.x - sh, v.y - sh, v.z - sh, v.w - sh);
}

// ---------------- BN coefficients (zeroes stats after reading) -------------
__global__ void bn_coef(const float* __restrict__ gamma,
                        const float* __restrict__ beta, float invM) {
    int f = threadIdx.x;
    float mu = g_stats[f] * invM;
    float var = g_stats[128 + f] * invM - mu * mu;
    float scl = gamma[f] * rsqrtf(var + 1e-5f);
    g_coef[f] = scl;
    g_coef[128 + f] = beta[f] - mu * scl;
    g_stats[f] = 0.f;
    g_stats[128 + f] = 0.f;
}

// ---------------- launch ----------------
extern "C" void kernel_launch(void* const* d_in, const int* in_sizes, int n_in,
                              void* d_out, int out_size) {
    const float* feats = (const float*)d_in[0];
    const int*   ei    = (const int*)d_in[1];
    const float* W1 = (const float*)d_in[2];
    const float* g1 = (const float*)d_in[4];
    const float* be1 = (const float*)d_in[5];
    const float* W2 = (const float*)d_in[6];
    const float* g2 = (const float*)d_in[8];
    const float* be2 = (const float*)d_in[9];
    const float* W3 = (const float*)d_in[10];
    const float* b3 = (const float*)d_in[11];
    float* out = (float*)d_out;

    const int Nn = in_sizes[0] / HID;
    const int Ee = in_sizes[1] / 2;

    float *bufB;
    __half *hA, *h3;
    cudaGetSymbolAddress((void**)&bufB, g_bufB);
    cudaGetSymbolAddress((void**)&hA, g_hA);
    cudaGetSymbolAddress((void**)&h3, g_h3);

    const float invM = 1.0f / (float)Nn;
    const int nb = (Nn + 1023) / 1024;
    const int AGG_BLOCKS = (Nn + 7) / 8;

    // ---- degree + CSR build (6 kernels) ----
    deg_init<<<(Nn + 255) / 256, 256>>>(Nn);
    deg_count<<<(Ee + 255) / 256, 256>>>(ei, Ee);
    scanA<<<nb, 1024>>>(Nn);
    scanB<<<1, 32>>>(nb);
    scanC<<<nb, 1024>>>(Nn);
    scatter_edges<<<(Ee + 255) / 256, 256>>>(ei, Ee);

    // ---- layer 1 ----
    gemm128_kernel<0><<<(Nn + 127) / 128, 256>>>(feats, W1, hA, Nn);
    agg_csr128<<<AGG_BLOCKS, 256>>>(hA, bufB, Nn);
    bn_coef<<<1, 128>>>(g1, be1, invM);

    // ---- layer 2 (BN1+ReLU fused into A-load) ----
    gemm128_kernel<1><<<(Nn + 127) / 128, 256>>>(bufB, W2, hA, Nn);
    agg_csr128<<<AGG_BLOCKS, 256>>>(hA, bufB, Nn);
    bn_coef<<<1, 128>>>(g2, be2, invM);

    // ---- layer 3 (BN2+ReLU fused into A-load) ----
    gemm40_kernel<<<(Nn + 31) / 32, 256>>>(bufB, W3, h3, Nn);
    agg40_logsm<<<AGG_BLOCKS, 256>>>(h3, b3, out, Nn);
}

// round 11
// speedup vs baseline: 1.3727x; 1.2102x over previous
#include <cuda_runtime.h>
#include <cuda_fp16.h>
#include <mma.h>
#include <math.h>

using namespace nvcuda;

#define NMAX 50000
#define EMAX 800000
#define HID  128
#define CO   40

// ---------------- scratch (device globals) ----------------
__device__ __align__(16) float  g_bufB[NMAX * HID];     // fp32 agg output
__device__ __align__(16) __half g_hA[NMAX * HID];       // fp16 gemm output (gather src)
__device__ __align__(16) __half g_h3[NMAX * CO];        // fp16 layer-3 gemm output
__device__ __align__(16) float  g_dinv[NMAX];
__device__ int   g_cnt[NMAX];
__device__ int   g_off[NMAX + 1];
__device__ int   g_cur[NMAX];
__device__ int   g_bsum[128];
__device__ int   g_csr_src[EMAX + NMAX];
__device__ float g_csr_coef[EMAX + NMAX];
__device__ __align__(16) float g_stats[2 * 256];        // two slots: [sum(128), sumsq(128)] each

// ---------------- degree (also zeroes both BN stat slots) ----------------
__global__ void deg_init(int n) {
    int i = blockIdx.x * blockDim.x + threadIdx.x;
    if (i < n) g_cnt[i] = 1;               // self loop
    if (i < 512) g_stats[i] = 0.0f;
}
__global__ void deg_count(const int* __restrict__ ei, int e) {
    int i = blockIdx.x * blockDim.x + threadIdx.x;
    if (i < e) atomicAdd(&g_cnt[ei[e + i]], 1);
}

// -------- scanA: block-level inclusive scan of cnt; also writes dinv -------
__global__ void scanA(int n) {
    __shared__ int wsum[32];
    const unsigned FULL = 0xffffffffu;
    int i = blockIdx.x * 1024 + threadIdx.x;
    int lane = threadIdx.x & 31, wid = threadIdx.x >> 5;
    int c = (i < n) ? g_cnt[i] : 0;
    if (i < n) g_dinv[i] = rsqrtf((float)c);
    int x = c;
#pragma unroll
    for (int o = 1; o < 32; o <<= 1) {
        int t = __shfl_up_sync(FULL, x, o);
        if (lane >= o) x += t;
    }
    if (lane == 31) wsum[wid] = x;
    __syncthreads();
    if (wid == 0) {
        int y = wsum[lane];
#pragma unroll
        for (int o = 1; o < 32; o <<= 1) {
            int t = __shfl_up_sync(FULL, y, o);
            if (lane >= o) y += t;
        }
        wsum[lane] = y;
    }
    __syncthreads();
    int inc = x + (wid ? wsum[wid - 1] : 0);
    if (i < n) g_off[i + 1] = inc;
    if (threadIdx.x == 1023) g_bsum[blockIdx.x] = inc;
}

// scanC: per-block redundant scan of block sums (absorbs scanB) + finalize
// offsets + cursor init + self-loop scatter, all in one pass.
__global__ void scanC(int n, int nb) {
    __shared__ int base_s;
    const unsigned FULL = 0xffffffffu;
    if (threadIdx.x < 32) {
        int lane = threadIdx.x;
        int i0 = 2 * lane, i1 = 2 * lane + 1;
        int v0 = (i0 < nb) ? g_bsum[i0] : 0;
        int v1 = (i1 < nb) ? g_bsum[i1] : 0;
        int s = v0 + v1;
        int x = s;
#pragma unroll
        for (int o = 1; o < 32; o <<= 1) {
            int t = __shfl_up_sync(FULL, x, o);
            if (lane >= o) x += t;
        }
        int excl = x - s;               // sum of pairs before this pair
        int bid = blockIdx.x;
        if (lane == (bid >> 1))
            base_s = excl + ((bid & 1) ? v0 : 0);
    }
    __syncthreads();
    int base = base_s;
    int i = blockIdx.x * 1024 + threadIdx.x;
    if (i < n) {
        int o = g_off[i + 1] + base;
        g_off[i + 1] = o;
        int c = g_cnt[i];
        int p = o - c;                  // exclusive offset of node i
        g_cur[i] = p + 1;
        g_csr_src[p] = i;
        float di = g_dinv[i];
        g_csr_coef[p] = di * di;
    }
    if (i == 0) g_off[0] = 0;
}
__global__ void scatter_edges(const int* __restrict__ ei, int e) {
    int i = blockIdx.x * blockDim.x + threadIdx.x;
    if (i < e) {
        int s = ei[i];
        int d = ei[e + i];
        int p = atomicAdd(&g_cur[d], 1);
        g_csr_src[p] = s;
        g_csr_coef[p] = g_dinv[s] * g_dinv[d];
    }
}

// ---- wmma fp16 GEMM 128x128: BM=128 BN=128, 256 thr, fp32 accum -----------
// BN!=0: apply BatchNorm(+ReLU) to A on load, coefs computed per block from
// g_stats slot (statsIdx) + gamma/beta.
#define WS_LD 136                     // padded halves per W row
#define AS_LD 24                      // padded halves per A-tile row
#define CS_LD 68                      // padded floats per C-staging row

template <int BN>
__global__ __launch_bounds__(256) void gemm128_wmma(
    const float* __restrict__ A, const float* __restrict__ W,
    __half* __restrict__ C, int M,
    const float* __restrict__ gamma, const float* __restrict__ beta,
    int statsIdx, float invM) {
    __shared__ __align__(16) unsigned char smem_raw[128 * WS_LD * 2 + 128 * AS_LD * 2];
    __shared__ float coefS[128], coefT[128];
    __half* Ws = (__half*)smem_raw;                       // [128][WS_LD]
    __half* As = (__half*)(smem_raw + 128 * WS_LD * 2);   // [128][AS_LD]
    float*  Cs = (float*)smem_raw;                        // [128][CS_LD] (reuse)

    const int tid = threadIdx.x;
    const int w = tid >> 5;
    const int warprow = w >> 1;         // 0..3 -> rows warprow*32
    const int warpcol = w & 1;          // 0..1 -> cols warpcol*64
    const int row0 = blockIdx.x * 128;

    if (BN) {
        if (tid < 128) {
            float mu = g_stats[statsIdx * 256 + tid] * invM;
            float var = g_stats[statsIdx * 256 + 128 + tid] * invM - mu * mu;
            float scl = gamma[tid] * rsqrtf(var + 1e-5f);
            coefS[tid] = scl;
            coefT[tid] = beta[tid] - mu * scl;
        }
    }
    // stage W (128x128 fp32 -> half, padded)
    for (int i = tid; i < 2048; i += 256) {
        int base = i * 8;
        int k = base >> 7, ncol = base & 127;
        float4 f0 = *(const float4*)(W + base);
        float4 f1 = *(const float4*)(W + base + 4);
        __half2 h0 = __floats2half2_rn(f0.x, f0.y);
        __half2 h1 = __floats2half2_rn(f0.z, f0.w);
        __half2 h2 = __floats2half2_rn(f1.x, f1.y);
        __half2 h3 = __floats2half2_rn(f1.z, f1.w);
        uint4 pk;
        pk.x = *(unsigned*)&h0; pk.y = *(unsigned*)&h1;
        pk.z = *(unsigned*)&h2; pk.w = *(unsigned*)&h3;
        *(uint4*)(Ws + k * WS_LD + ncol) = pk;
    }
    __syncthreads();

    wmma::fragment<wmma::accumulator, 16, 16, 16, float> acc[2][4];
#pragma unroll
    for (int i = 0; i < 2; i++)
#pragma unroll
        for (int j = 0; j < 4; j++) wmma::fill_fragment(acc[i][j], 0.0f);

    const int arow = tid >> 1;
    const int acol = (tid & 1) << 3;    // 0 or 8

    for (int kk = 0; kk < 128; kk += 16) {
        // A tile 128x16 -> half (BN fused)
        int gr = row0 + arow;
        float4 f0 = make_float4(0.f, 0.f, 0.f, 0.f), f1 = f0;
        if (gr < M) {
            f0 = *(const float4*)(A + (size_t)gr * 128 + kk + acol);
            f1 = *(const float4*)(A + (size_t)gr * 128 + kk + acol + 4);
        }
        if (BN) {
            int c0 = kk + acol;
            f0.x = fmaxf(fmaf(f0.x, coefS[c0 + 0], coefT[c0 + 0]), 0.f);
            f0.y = fmaxf(fmaf(f0.y, coefS[c0 + 1], coefT[c0 + 1]), 0.f);
            f0.z = fmaxf(fmaf(f0.z, coefS[c0 + 2], coefT[c0 + 2]), 0.f);
            f0.w = fmaxf(fmaf(f0.w, coefS[c0 + 3], coefT[c0 + 3]), 0.f);
            f1.x = fmaxf(fmaf(f1.x, coefS[c0 + 4], coefT[c0 + 4]), 0.f);
            f1.y = fmaxf(fmaf(f1.y, coefS[c0 + 5], coefT[c0 + 5]), 0.f);
            f1.z = fmaxf(fmaf(f1.z, coefS[c0 + 6], coefT[c0 + 6]), 0.f);
            f1.w = fmaxf(fmaf(f1.w, coefS[c0 + 7], coefT[c0 + 7]), 0.f);
        }
        {
            __half2 h0 = __floats2half2_rn(f0.x, f0.y);
            __half2 h1 = __floats2half2_rn(f0.z, f0.w);
            __half2 h2 = __floats2half2_rn(f1.x, f1.y);
            __half2 h3 = __floats2half2_rn(f1.z, f1.w);
            uint4 pk;
            pk.x = *(unsigned*)&h0; pk.y = *(unsigned*)&h1;
            pk.z = *(unsigned*)&h2; pk.w = *(unsigned*)&h3;
            *(uint4*)(As + arow * AS_LD + acol) = pk;
        }
        __syncthreads();
        wmma::fragment<wmma::matrix_a, 16, 16, 16, __half, wmma::row_major> af[2];
#pragma unroll
        for (int i = 0; i < 2; i++)
            wmma::load_matrix_sync(af[i], As + (warprow * 32 + i * 16) * AS_LD, AS_LD);
#pragma unroll
        for (int j = 0; j < 4; j++) {
            wmma::fragment<wmma::matrix_b, 16, 16, 16, __half, wmma::row_major> bf;
            wmma::load_matrix_sync(bf, Ws + kk * WS_LD + warpcol * 64 + j * 16, WS_LD);
#pragma unroll
            for (int i = 0; i < 2; i++)
                wmma::mma_sync(acc[i][j], af[i], bf, acc[i][j]);
        }
        __syncthreads();
    }

    // store: two rounds through Cs (reuses Ws region)
#pragma unroll
    for (int r = 0; r < 2; r++) {
        if (warpcol == r) {
#pragma unroll
            for (int i = 0; i < 2; i++)
#pragma unroll
                for (int j = 0; j < 4; j++)
                    wmma::store_matrix_sync(
                        Cs + (warprow * 32 + i * 16) * CS_LD + j * 16,
                        acc[i][j], CS_LD, wmma::mem_row_major);
        }
        __syncthreads();
        int row = tid >> 1;
        int gr = row0 + row;
        if (gr < M) {
            const float* src = Cs + row * CS_LD + (tid & 1) * 32;
            __half* dst = C + (size_t)gr * 128 + r * 64 + (tid & 1) * 32;
#pragma unroll
            for (int q = 0; q < 4; q++) {
                float4 fa = ((const float4*)src)[2 * q];
                float4 fb = ((const float4*)src)[2 * q + 1];
                __half2 h0 = __floats2half2_rn(fa.x, fa.y);
                __half2 h1 = __floats2half2_rn(fa.z, fa.w);
                __half2 h2 = __floats2half2_rn(fb.x, fb.y);
                __half2 h3 = __floats2half2_rn(fb.z, fb.w);
                uint4 pk;
                pk.x = *(unsigned*)&h0; pk.y = *(unsigned*)&h1;
                pk.z = *(unsigned*)&h2; pk.w = *(unsigned*)&h3;
                ((uint4*)dst)[q] = pk;
            }
        }
        __syncthreads();
    }
}

// ------- SGEMM 128x40 (BN2+ReLU fused on A, coefs computed in-block) -------
__global__ void gemm40_kernel(const float* __restrict__ A,
                              const float* __restrict__ W,
                              __half* __restrict__ C, int M,
                              const float* __restrict__ gamma,
                              const float* __restrict__ beta, float invM) {
    __shared__ float Xs[32][133];
    __shared__ float Ws[128 * 40];
    __shared__ float coefS[128], coefT[128];
    const int tid = threadIdx.x;
    const int row0 = blockIdx.x * 32;

    if (tid < 128) {
        float mu = g_stats[256 + tid] * invM;
        float var = g_stats[256 + 128 + tid] * invM - mu * mu;
        float scl = gamma[tid] * rsqrtf(var + 1e-5f);
        coefS[tid] = scl;
        coefT[tid] = beta[tid] - mu * scl;
    }
    for (int i = tid; i < 128 * 40; i += 256) Ws[i] = W[i];
    __syncthreads();
#pragma unroll
    for (int i = 0; i < 4; i++) {
        int v = tid + i * 256;
        int r = v >> 5, c = (v & 31) << 2;
        float4 xv = make_float4(0.f, 0.f, 0.f, 0.f);
        int gr = row0 + r;
        if (gr < M) xv = *(const float4*)(A + (size_t)gr * 128 + c);
        Xs[r][c + 0] = fmaxf(fmaf(xv.x, coefS[c + 0], coefT[c + 0]), 0.f);
        Xs[r][c + 1] = fmaxf(fmaf(xv.y, coefS[c + 1], coefT[c + 1]), 0.f);
        Xs[r][c + 2] = fmaxf(fmaf(xv.z, coefS[c + 2], coefT[c + 2]), 0.f);
        Xs[r][c + 3] = fmaxf(fmaf(xv.w, coefS[c + 3], coefT[c + 3]), 0.f);
    }
    __syncthreads();

    const int r = tid >> 3;
    const int cg = tid & 7;
    float acc[5] = {0.f, 0.f, 0.f, 0.f, 0.f};
#pragma unroll 8
    for (int k = 0; k < 128; k++) {
        float xv = Xs[r][k];
        const float* wr = &Ws[k * 40 + cg * 5];
#pragma unroll
        for (int c = 0; c < 5; c++) acc[c] = fmaf(xv, wr[c], acc[c]);
    }
    int gr = row0 + r;
    if (gr < M) {
        __half* outp = C + (size_t)gr * 40 + cg * 5;
#pragma unroll
        for (int c = 0; c < 5; c++) outp[c] = __float2half_rn(acc[c]);
    }
}

// ---- CSR gather aggregation from fp16 H, fused BN-stats, fp32 out ---------
__global__ __launch_bounds__(256) void agg_csr128(
    const __half* __restrict__ H, float* __restrict__ Agg, int n, int slot) {
    __shared__ float sh_s[128], sh_s2[128];
    if (threadIdx.x < 128) { sh_s[threadIdx.x] = 0.f; sh_s2[threadIdx.x] = 0.f; }
    __syncthreads();
    int warp = (blockIdx.x * blockDim.x + threadIdx.x) >> 5;
    int lane = threadIdx.x & 31;
    float4 acc = make_float4(0.f, 0.f, 0.f, 0.f);
    bool active = (warp < n);
    if (active) {
        int beg = g_off[warp], end = g_off[warp + 1];
        int e = beg;
        for (; e + 3 < end; e += 4) {
            int   s0 = g_csr_src[e],      s1 = g_csr_src[e + 1];
            int   s2 = g_csr_src[e + 2],  s3 = g_csr_src[e + 3];
            float c0 = g_csr_coef[e],     c1 = g_csr_coef[e + 1];
            float c2 = g_csr_coef[e + 2], c3 = g_csr_coef[e + 3];
            uint2 r0 = ((const uint2*)(H + (size_t)s0 * 128))[lane];
            uint2 r1 = ((const uint2*)(H + (size_t)s1 * 128))[lane];
            uint2 r2 = ((const uint2*)(H + (size_t)s2 * 128))[lane];
            uint2 r3 = ((const uint2*)(H + (size_t)s3 * 128))[lane];
            float2 a0 = __half22float2(*(__half2*)&r0.x), b0 = __half22float2(*(__half2*)&r0.y);
            float2 a1 = __half22float2(*(__half2*)&r1.x), b1 = __half22float2(*(__half2*)&r1.y);
            float2 a2 = __half22float2(*(__half2*)&r2.x), b2 = __half22float2(*(__half2*)&r2.y);
            float2 a3 = __half22float2(*(__half2*)&r3.x), b3v = __half22float2(*(__half2*)&r3.y);
            acc.x = fmaf(a0.x, c0, fmaf(a1.x, c1, fmaf(a2.x, c2, fmaf(a3.x, c3, acc.x))));
            acc.y = fmaf(a0.y, c0, fmaf(a1.y, c1, fmaf(a2.y, c2, fmaf(a3.y, c3, acc.y))));
            acc.z = fmaf(b0.x, c0, fmaf(b1.x, c1, fmaf(b2.x, c2, fmaf(b3v.x, c3, acc.z))));
            acc.w = fmaf(b0.y, c0, fmaf(b1.y, c1, fmaf(b2.y, c2, fmaf(b3v.y, c3, acc.w))));
        }
        for (; e < end; e++) {
            int s0 = g_csr_src[e];
            float c0 = g_csr_coef[e];
            uint2 r0 = ((const uint2*)(H + (size_t)s0 * 128))[lane];
            float2 a0 = __half22float2(*(__half2*)&r0.x), b0 = __half22float2(*(__half2*)&r0.y);
            acc.x = fmaf(a0.x, c0, acc.x);
            acc.y = fmaf(a0.y, c0, acc.y);
            acc.z = fmaf(b0.x, c0, acc.z);
            acc.w = fmaf(b0.y, c0, acc.w);
        }
        ((float4*)(Agg + (size_t)warp * 128))[lane] = acc;
        int col = lane << 2;
        atomicAdd(&sh_s[col + 0], acc.x);  atomicAdd(&sh_s2[col + 0], acc.x * acc.x);
        atomicAdd(&sh_s[col + 1], acc.y);  atomicAdd(&sh_s2[col + 1], acc.y * acc.y);
        atomicAdd(&sh_s[col + 2], acc.z);  atomicAdd(&sh_s2[col + 2], acc.z * acc.z);
        atomicAdd(&sh_s[col + 3], acc.w);  atomicAdd(&sh_s2[col + 3], acc.w * acc.w);
    }
    __syncthreads();
    if (threadIdx.x < 128) {
        atomicAdd(&g_stats[slot * 256 + threadIdx.x], sh_s[threadIdx.x]);
        atomicAdd(&g_stats[slot * 256 + 128 + threadIdx.x], sh_s2[threadIdx.x]);
    }
}

// ---- fused agg40 + bias + log-softmax: warp per node ----------------------
__global__ void agg40_logsm(const __half* __restrict__ H,
                            const float* __restrict__ b3,
                            float* __restrict__ out, int n) {
    const unsigned FULL = 0xffffffffu;
    int warp = (blockIdx.x * blockDim.x + threadIdx.x) >> 5;
    int lane = threadIdx.x & 31;
    if (warp >= n) return;
    int beg = g_off[warp], end = g_off[warp + 1];
    float4 acc = make_float4(0.f, 0.f, 0.f, 0.f);
    for (int e = beg; e < end; e++) {
        int s0 = g_csr_src[e];
        float c0 = g_csr_coef[e];
        if (lane < 10) {
            uint2 r0 = ((const uint2*)(H + (size_t)s0 * 40))[lane];
            float2 a0 = __half22float2(*(__half2*)&r0.x);
            float2 b0 = __half22float2(*(__half2*)&r0.y);
            acc.x = fmaf(a0.x, c0, acc.x);
            acc.y = fmaf(a0.y, c0, acc.y);
            acc.z = fmaf(b0.x, c0, acc.z);
            acc.w = fmaf(b0.y, c0, acc.w);
        }
    }
    float4 v = make_float4(-3.0e38f, -3.0e38f, -3.0e38f, -3.0e38f);
    if (lane < 10) {
        float4 bb = ((const float4*)b3)[lane];
        v = make_float4(acc.x + bb.x, acc.y + bb.y, acc.z + bb.z, acc.w + bb.w);
    }
    float mx = fmaxf(fmaxf(v.x, v.y), fmaxf(v.z, v.w));
#pragma unroll
    for (int o = 16; o; o >>= 1) mx = fmaxf(mx, __shfl_xor_sync(FULL, mx, o));
    float se = 0.f;
    if (lane < 10)
        se = expf(v.x - mx) + expf(v.y - mx) + expf(v.z - mx) + expf(v.w - mx);
#pragma unroll
    for (int o = 16; o; o >>= 1) se += __shfl_xor_sync(FULL, se, o);
    float sh = mx + logf(se);
    if (lane < 10)
        ((float4*)(out + (size_t)warp * 40))[lane] =
            make_float4(v.x - sh, v.y - sh, v.z - sh, v.w - sh);
}

// ---------------- launch ----------------
extern "C" void kernel_launch(void* const* d_in, const int* in_sizes, int n_in,
                              void* d_out, int out_size) {
    const float* feats = (const float*)d_in[0];
    const int*   ei    = (const int*)d_in[1];
    const float* W1 = (const float*)d_in[2];
    const float* g1 = (const float*)d_in[4];
    const float* be1 = (const float*)d_in[5];
    const float* W2 = (const float*)d_in[6];
    const float* g2 = (const float*)d_in[8];
    const float* be2 = (const float*)d_in[9];
    const float* W3 = (const float*)d_in[10];
    const float* b3 = (const float*)d_in[11];
    float* out = (float*)d_out;

    const int Nn = in_sizes[0] / HID;
    const int Ee = in_sizes[1] / 2;

    float *bufB;
    __half *hA, *h3;
    cudaGetSymbolAddress((void**)&bufB, g_bufB);
    cudaGetSymbolAddress((void**)&hA, g_hA);
    cudaGetSymbolAddress((void**)&h3, g_h3);

    const float invM = 1.0f / (float)Nn;
    const int nb = (Nn + 1023) / 1024;
    const int AGG_BLOCKS = (Nn + 7) / 8;

    // ---- degree + CSR build (5 kernels) ----
    deg_init<<<(Nn + 255) / 256, 256>>>(Nn);
    deg_count<<<(Ee + 255) / 256, 256>>>(ei, Ee);
    scanA<<<nb, 1024>>>(Nn);
    scanC<<<nb, 1024>>>(Nn, nb);
    scatter_edges<<<(Ee + 255) / 256, 256>>>(ei, Ee);

    // ---- layer 1 ----
    gemm128_wmma<0><<<(Nn + 127) / 128, 256>>>(feats, W1, hA, Nn,
                                               nullptr, nullptr, 0, invM);
    agg_csr128<<<AGG_BLOCKS, 256>>>(hA, bufB, Nn, 0);

    // ---- layer 2 (BN1+ReLU fused into A-load, coefs from stats slot 0) ----
    gemm128_wmma<1><<<(Nn + 127) / 128, 256>>>(bufB, W2, hA, Nn,
                                               g1, be1, 0, invM);
    agg_csr128<<<AGG_BLOCKS, 256>>>(hA, bufB, Nn, 1);

    // ---- layer 3 (BN2+ReLU fused, coefs from stats slot 1) ----
    gemm40_kernel<<<(Nn + 31) / 32, 256>>>(bufB, W3, h3, Nn, g2, be2, invM);
    agg40_logsm<<<AGG_BLOCKS, 256>>>(h3, b3, out, Nn);
}